// round 2
// baseline (speedup 1.0000x reference)
#include <cuda_runtime.h>
#include <cstdint>
#include <cstddef>

// Problem dims
#define Bdim 64
#define Ndim 64
#define Cdim 8
#define Fdim 256
#define Kdim 2048           // C*F
#define Mrows 4160          // B*(N+1): row 0 of each b = x, rows 1..64 = neighbors
#define MrowsPad 4224       // 33*128 for GEMM tiling (padded rows stay zero)

// Scratch (static device globals; zero-initialized at module load)
__device__ float g_w[Bdim * Ndim];                         // w[b,n]
__device__ float g_t[Bdim * Kdim];                         // t[b,c,d]
__device__ float g_adj[(size_t)Bdim * Cdim * Fdim * Fdim]; // adj[b,c,i,j] (symmetric in i,j) ~134MB
__device__ float g_z[(size_t)MrowsPad * Kdim];             // z[row][c*F+a]; rows >=4160 remain 0

// ---------------------------------------------------------------------------
// K1: w[b,n] = s1[b] * s2[b,n]
//     s1[b] = sum_{c,f} x[b,c,f]*w1sum[f], w1sum[f] = sum_c W1[c,f]; same for s2.
// grid (64, 8) x 256 threads; each warp handles one n.
// ---------------------------------------------------------------------------
__global__ void k1_w(const float* __restrict__ x, const float* __restrict__ nb,
                     const float* __restrict__ W1, const float* __restrict__ W2) {
    __shared__ float w1s[Fdim], w2s[Fdim], red[256];
    int b = blockIdx.x, ng = blockIdx.y;
    int t = threadIdx.x;
    float a1 = 0.f, a2 = 0.f;
#pragma unroll
    for (int c = 0; c < Cdim; ++c) { a1 += W1[c * Fdim + t]; a2 += W2[c * Fdim + t]; }
    w1s[t] = a1; w2s[t] = a2;
    __syncthreads();
    float s = 0.f;
#pragma unroll
    for (int c = 0; c < Cdim; ++c) s += x[b * Kdim + c * Fdim + t] * w1s[t];
    red[t] = s; __syncthreads();
    for (int st = 128; st > 0; st >>= 1) {
        if (t < st) red[t] += red[t + st];
        __syncthreads();
    }
    float s1 = red[0];
    int warp = t >> 5, lane = t & 31;
    int n = ng * 8 + warp;
    const float* p = nb + ((size_t)(b * Ndim + n)) * Kdim;
    float acc = 0.f;
    for (int i = lane; i < Kdim; i += 32) acc += p[i] * w2s[i & (Fdim - 1)];
#pragma unroll
    for (int o = 16; o > 0; o >>= 1) acc += __shfl_xor_sync(0xffffffffu, acc, o);
    if (lane == 0) g_w[b * Ndim + n] = s1 * acc;
}

// ---------------------------------------------------------------------------
// K2: t[b,cd] = sum_n neighbor[b,n,cd] * w[b,n]     grid (64,2) x 1024
// ---------------------------------------------------------------------------
__global__ void k2_t(const float* __restrict__ nb) {
    __shared__ float ws[Ndim];
    int b = blockIdx.x;
    int cd = blockIdx.y * 1024 + threadIdx.x;
    if (threadIdx.x < Ndim) ws[threadIdx.x] = g_w[b * Ndim + threadIdx.x];
    __syncthreads();
    const float* p = nb + (size_t)b * Ndim * Kdim + cd;
    float acc = 0.f;
#pragma unroll 8
    for (int n = 0; n < Ndim; ++n) acc += p[(size_t)n * Kdim] * ws[n];
    g_t[b * Kdim + cd] = acc;
}

// ---------------------------------------------------------------------------
// K3: adj[b,c,a,d] = sg_c / (sum_c |sg_c| + 1e-7),
//     sg_c = sign(v)*sqrt(max(|v|,1e-8)), v = x[c,a]t[c,d] + x[c,d]t[c,a]
// grid (64, 64) x 1024; thread owns one (a,d), loops c in registers.
// ---------------------------------------------------------------------------
__global__ void k3_adj(const float* __restrict__ x) {
    __shared__ float xs[Kdim], ts[Kdim];
    int b = blockIdx.x, t = threadIdx.x;
    xs[t] = x[b * Kdim + t];               xs[t + 1024] = x[b * Kdim + t + 1024];
    ts[t] = g_t[b * Kdim + t];             ts[t + 1024] = g_t[b * Kdim + t + 1024];
    __syncthreads();
    int idx = blockIdx.y * 1024 + t;
    int a = idx >> 8, d = idx & 255;
    float sg[Cdim];
    float nrm = 0.f;
#pragma unroll
    for (int c = 0; c < Cdim; ++c) {
        float v = xs[c * Fdim + a] * ts[c * Fdim + d] + xs[c * Fdim + d] * ts[c * Fdim + a];
        float r;
        asm("sqrt.approx.f32 %0, %1;" : "=f"(r) : "f"(fmaxf(fabsf(v), 1e-8f)));
        r = copysignf(r, v);
        sg[c] = r;
        nrm += fabsf(r);
    }
    float rinv = 1.0f / (nrm + 1e-7f);
    size_t base = ((size_t)b * Cdim) * 65536 + idx;
#pragma unroll
    for (int c = 0; c < Cdim; ++c) g_adj[base + (size_t)c * 65536] = sg[c] * rinv;
}

// ---------------------------------------------------------------------------
// K4: z[b*65+m][c*256+a] = sum_d adj[b,c,a,d] * src[m,d]
//     src row 0 = x[b,c,:], rows 1..64 = neighbor[b,:,c,:]
// grid (atile=2, c=8, b=64) x 256. Thread tile: 4 a's x 8 m's (mg==7 also m=64).
// Uses adj symmetry: reads adj[b,c,d,a] with a contiguous (coalesced).
// ---------------------------------------------------------------------------
#define DT 32
__global__ void __launch_bounds__(256) k4_z(const float* __restrict__ x,
                                            const float* __restrict__ nb) {
    __shared__ float srcS[65 * DT];    // [row][dd]
    __shared__ float adjS[DT * 128];   // [dd][la]
    int atile = blockIdx.x;
    int c = blockIdx.y;
    int b = blockIdx.z;
    int t = threadIdx.x;
    int ag = t & 31;
    int mg = t >> 5;          // warp id == m-group (whole warp shares mg)
    int a0 = atile * 128;
    int la = ag * 4;

    float acc[8][4] = {};
    float accx[4] = {};

    const float* xrow = x + ((size_t)b * Cdim + c) * Fdim;
    const float* nbase = nb + (((size_t)b * Ndim) * Cdim + c) * Fdim;
    const float* adjbase = g_adj + ((size_t)(b * Cdim + c)) * 65536 + a0;

    for (int d0 = 0; d0 < Fdim; d0 += DT) {
        for (int idx = t; idx < 65 * DT; idx += 256) {
            int row = idx >> 5, col = idx & (DT - 1);
            float v = (row == 0) ? xrow[d0 + col]
                                 : nbase[(size_t)(row - 1) * Kdim + d0 + col];
            srcS[idx] = v;
        }
        for (int idx = t; idx < DT * 128; idx += 256) {
            int dd = idx >> 7, l = idx & 127;
            adjS[idx] = adjbase[(size_t)(d0 + dd) * Fdim + l];
        }
        __syncthreads();
#pragma unroll 4
        for (int dd = 0; dd < DT; ++dd) {
            float4 av = *(const float4*)&adjS[dd * 128 + la];
#pragma unroll
            for (int j = 0; j < 8; ++j) {
                float s = srcS[(mg * 8 + j) * DT + dd];
                acc[j][0] += av.x * s; acc[j][1] += av.y * s;
                acc[j][2] += av.z * s; acc[j][3] += av.w * s;
            }
            if (mg == 7) {
                float s = srcS[64 * DT + dd];
                accx[0] += av.x * s; accx[1] += av.y * s;
                accx[2] += av.z * s; accx[3] += av.w * s;
            }
        }
        __syncthreads();
    }
#pragma unroll
    for (int j = 0; j < 8; ++j) {
        int m = mg * 8 + j;
        float4 v = make_float4(acc[j][0], acc[j][1], acc[j][2], acc[j][3]);
        *(float4*)&g_z[((size_t)(b * 65 + m)) * Kdim + c * Fdim + a0 + la] = v;
    }
    if (mg == 7) {
        float4 v = make_float4(accx[0], accx[1], accx[2], accx[3]);
        *(float4*)&g_z[((size_t)(b * 65 + 64)) * Kdim + c * Fdim + a0 + la] = v;
    }
}

// ---------------------------------------------------------------------------
// K5: out GEMM: out[row][o] = sum_k z[row][k] * Wc[o][k]   (NT, both K-major)
//     M=4160 (padded 4224), N=2048, K=2048. 128x128 tile, 8x8 per thread.
//     Row r = b*65+m maps to: m==0 -> x_out[b], else n_out[b, m-1].
// grid (16, 33) x 256
// ---------------------------------------------------------------------------
__global__ void __launch_bounds__(256, 2) k5_gemm(const float* __restrict__ Wc,
                                                  float* __restrict__ out) {
    __shared__ float As[8][128], Bs[8][128];
    int t = threadIdx.x;
    int bn = blockIdx.x, bm = blockIdx.y;
    int lrow = t >> 1;
    int lk = (t & 1) * 4;
    const float* Ap = g_z + ((size_t)(bm * 128 + lrow)) * Kdim + lk;
    const float* Bp = Wc + ((size_t)(bn * 128 + lrow)) * Kdim + lk;
    int tx = t & 15, ty = t >> 4;
    float acc[8][8] = {};

    float4 av = *(const float4*)(Ap);
    float4 bv = *(const float4*)(Bp);
    for (int kt = 0; kt < Kdim; kt += 8) {
        As[lk + 0][lrow] = av.x; As[lk + 1][lrow] = av.y;
        As[lk + 2][lrow] = av.z; As[lk + 3][lrow] = av.w;
        Bs[lk + 0][lrow] = bv.x; Bs[lk + 1][lrow] = bv.y;
        Bs[lk + 2][lrow] = bv.z; Bs[lk + 3][lrow] = bv.w;
        __syncthreads();
        float4 av2 = av, bv2 = bv;
        if (kt + 8 < Kdim) {
            av2 = *(const float4*)(Ap + kt + 8);
            bv2 = *(const float4*)(Bp + kt + 8);
        }
#pragma unroll
        for (int k = 0; k < 8; ++k) {
            float4 a0 = *(const float4*)&As[k][ty * 8];
            float4 a1 = *(const float4*)&As[k][ty * 8 + 4];
            float4 b0 = *(const float4*)&Bs[k][tx * 8];
            float4 b1 = *(const float4*)&Bs[k][tx * 8 + 4];
            float ar[8] = {a0.x, a0.y, a0.z, a0.w, a1.x, a1.y, a1.z, a1.w};
            float br[8] = {b0.x, b0.y, b0.z, b0.w, b1.x, b1.y, b1.z, b1.w};
#pragma unroll
            for (int i = 0; i < 8; ++i)
#pragma unroll
                for (int j = 0; j < 8; ++j)
                    acc[i][j] += ar[i] * br[j];
        }
        __syncthreads();
        av = av2; bv = bv2;
    }
#pragma unroll
    for (int i = 0; i < 8; ++i) {
        int r = bm * 128 + ty * 8 + i;
        if (r >= Mrows) continue;
        int b = r / 65, m = r % 65;
        size_t off;
        if (m == 0) off = (size_t)b * 2048;
        else        off = (size_t)131072 + ((size_t)(b * 64 + m - 1)) * 2048;
        float4 v0 = make_float4(acc[i][0], acc[i][1], acc[i][2], acc[i][3]);
        float4 v1 = make_float4(acc[i][4], acc[i][5], acc[i][6], acc[i][7]);
        *(float4*)&out[off + bn * 128 + tx * 8] = v0;
        *(float4*)&out[off + bn * 128 + tx * 8 + 4] = v1;
    }
}

// ---------------------------------------------------------------------------
extern "C" void kernel_launch(void* const* d_in, const int* in_sizes, int n_in,
                              void* d_out, int out_size) {
    const float* x  = (const float*)d_in[0];
    const float* nb = (const float*)d_in[1];
    const float* W1 = (const float*)d_in[2];
    const float* W2 = (const float*)d_in[3];
    const float* Wc = (const float*)d_in[4];
    float* out = (float*)d_out;

    k1_w  <<<dim3(64, 8),      256 >>>(x, nb, W1, W2);
    k2_t  <<<dim3(64, 2),     1024 >>>(nb);
    k3_adj<<<dim3(64, 64),    1024 >>>(x);
    k4_z  <<<dim3(2, 8, 64),   256 >>>(x, nb);
    k5_gemm<<<dim3(16, 33),    256 >>>(Wc, out);
}

// round 10
// speedup vs baseline: 1.9400x; 1.9400x over previous
#include <cuda_runtime.h>
#include <cuda_bf16.h>
#include <cstdint>
#include <cstddef>

// Problem dims
#define Bdim 64
#define Ndim 64
#define Cdim 8
#define Fdim 256
#define Kdim 2048           // C*F
#define Mrows 4160          // B*(N+1): row 0 of each b = x, rows 1..64 = neighbors
#define MrowsPad 4224       // 33*128 for GEMM tiling (padded rows stay zero)

// Scratch (static device globals; zero-initialized at module load).
// __align__(256): k0/k4/k5 use 16B vector accesses; device globals only
// guarantee natural alignment of the element type without this.
__device__ float g_w[Bdim * Ndim];                                        // w[b,n]
__device__ float g_t[Bdim * Kdim];                                        // t[b,c,d]
__device__ __align__(256) float g_adj[(size_t)Bdim * Cdim * Fdim * Fdim]; // adj (~134MB)
__device__ __align__(256) __nv_bfloat16 g_zh[(size_t)MrowsPad * Kdim];    // z hi split
__device__ __align__(256) __nv_bfloat16 g_zl[(size_t)MrowsPad * Kdim];    // z lo split
__device__ __align__(256) __nv_bfloat16 g_wh[(size_t)Kdim * Kdim];        // Wc hi [o][k]
__device__ __align__(256) __nv_bfloat16 g_wl[(size_t)Kdim * Kdim];        // Wc lo [o][k]

// ---------------------------------------------------------------------------
// mma.sync helpers (arch-portable tensor core path; harness PTX target is
// plain sm_103 so tcgen05 is unavailable)
// ---------------------------------------------------------------------------
__device__ __forceinline__ uint32_t smem_u32(const void* p) {
    uint32_t a;
    asm("{ .reg .u64 t; cvta.to.shared.u64 t, %1; cvt.u32.u64 %0, t; }" : "=r"(a) : "l"(p));
    return a;
}
__device__ __forceinline__ void ldm_x4(uint32_t a, uint32_t f[4]) {
    asm volatile("ldmatrix.sync.aligned.m8n8.x4.shared.b16 {%0,%1,%2,%3}, [%4];"
                 : "=r"(f[0]), "=r"(f[1]), "=r"(f[2]), "=r"(f[3]) : "r"(a));
}
__device__ __forceinline__ void ldm_x2(uint32_t a, uint32_t f[2]) {
    asm volatile("ldmatrix.sync.aligned.m8n8.x2.shared.b16 {%0,%1}, [%2];"
                 : "=r"(f[0]), "=r"(f[1]) : "r"(a));
}
__device__ __forceinline__ void mma16816(float d[4], const uint32_t a[4],
                                         const uint32_t b[2]) {
    asm volatile(
        "mma.sync.aligned.m16n8k16.row.col.f32.bf16.bf16.f32 "
        "{%0,%1,%2,%3},{%4,%5,%6,%7},{%8,%9},{%0,%1,%2,%3};"
        : "+f"(d[0]), "+f"(d[1]), "+f"(d[2]), "+f"(d[3])
        : "r"(a[0]), "r"(a[1]), "r"(a[2]), "r"(a[3]), "r"(b[0]), "r"(b[1]));
}

// ---------------------------------------------------------------------------
// K0: split Wc (2048x2048 f32) into bf16 hi/lo. grid 4096 x 256 (float4/thread)
// ---------------------------------------------------------------------------
__global__ void k0_split(const float* __restrict__ Wc) {
    size_t i = (size_t)blockIdx.x * 256 + threadIdx.x;   // float4 index
    float4 v = ((const float4*)Wc)[i];
    __nv_bfloat16 h0 = __float2bfloat16(v.x), h1 = __float2bfloat16(v.y);
    __nv_bfloat16 h2 = __float2bfloat16(v.z), h3 = __float2bfloat16(v.w);
    __nv_bfloat162 hp0 = {h0, h1}, hp1 = {h2, h3};
    __nv_bfloat162 lp0 = {__float2bfloat16(v.x - __bfloat162float(h0)),
                          __float2bfloat16(v.y - __bfloat162float(h1))};
    __nv_bfloat162 lp1 = {__float2bfloat16(v.z - __bfloat162float(h2)),
                          __float2bfloat16(v.w - __bfloat162float(h3))};
    ((__nv_bfloat162*)g_wh)[i * 2] = hp0; ((__nv_bfloat162*)g_wh)[i * 2 + 1] = hp1;
    ((__nv_bfloat162*)g_wl)[i * 2] = lp0; ((__nv_bfloat162*)g_wl)[i * 2 + 1] = lp1;
}

// ---------------------------------------------------------------------------
// K1: w[b,n] = s1[b] * s2[b,n]
// ---------------------------------------------------------------------------
__global__ void k1_w(const float* __restrict__ x, const float* __restrict__ nb,
                     const float* __restrict__ W1, const float* __restrict__ W2) {
    __shared__ float w1s[Fdim], w2s[Fdim], red[256];
    int b = blockIdx.x, ng = blockIdx.y;
    int t = threadIdx.x;
    float a1 = 0.f, a2 = 0.f;
#pragma unroll
    for (int c = 0; c < Cdim; ++c) { a1 += W1[c * Fdim + t]; a2 += W2[c * Fdim + t]; }
    w1s[t] = a1; w2s[t] = a2;
    __syncthreads();
    float s = 0.f;
#pragma unroll
    for (int c = 0; c < Cdim; ++c) s += x[b * Kdim + c * Fdim + t] * w1s[t];
    red[t] = s; __syncthreads();
    for (int st = 128; st > 0; st >>= 1) {
        if (t < st) red[t] += red[t + st];
        __syncthreads();
    }
    float s1 = red[0];
    int warp = t >> 5, lane = t & 31;
    int n = ng * 8 + warp;
    const float* p = nb + ((size_t)(b * Ndim + n)) * Kdim;
    float acc = 0.f;
    for (int i = lane; i < Kdim; i += 32) acc += p[i] * w2s[i & (Fdim - 1)];
#pragma unroll
    for (int o = 16; o > 0; o >>= 1) acc += __shfl_xor_sync(0xffffffffu, acc, o);
    if (lane == 0) g_w[b * Ndim + n] = s1 * acc;
}

// ---------------------------------------------------------------------------
// K2: t[b,cd] = sum_n neighbor[b,n,cd] * w[b,n]     grid (64,2) x 1024
// ---------------------------------------------------------------------------
__global__ void k2_t(const float* __restrict__ nb) {
    __shared__ float ws[Ndim];
    int b = blockIdx.x;
    int cd = blockIdx.y * 1024 + threadIdx.x;
    if (threadIdx.x < Ndim) ws[threadIdx.x] = g_w[b * Ndim + threadIdx.x];
    __syncthreads();
    const float* p = nb + (size_t)b * Ndim * Kdim + cd;
    float acc = 0.f;
#pragma unroll 8
    for (int n = 0; n < Ndim; ++n) acc += p[(size_t)n * Kdim] * ws[n];
    g_t[b * Kdim + cd] = acc;
}

// ---------------------------------------------------------------------------
// K3: adj[b,c,a,d] = sgnroot(x_a t_d + x_d t_a) row-normalized over c
// ---------------------------------------------------------------------------
__global__ void k3_adj(const float* __restrict__ x) {
    __shared__ float xs[Kdim], ts[Kdim];
    int b = blockIdx.x, t = threadIdx.x;
    xs[t] = x[b * Kdim + t];               xs[t + 1024] = x[b * Kdim + t + 1024];
    ts[t] = g_t[b * Kdim + t];             ts[t + 1024] = g_t[b * Kdim + t + 1024];
    __syncthreads();
    int idx = blockIdx.y * 1024 + t;
    int a = idx >> 8, d = idx & 255;
    float sg[Cdim];
    float nrm = 0.f;
#pragma unroll
    for (int c = 0; c < Cdim; ++c) {
        float v = xs[c * Fdim + a] * ts[c * Fdim + d] + xs[c * Fdim + d] * ts[c * Fdim + a];
        float r;
        asm("sqrt.approx.f32 %0, %1;" : "=f"(r) : "f"(fmaxf(fabsf(v), 1e-8f)));
        r = copysignf(r, v);
        sg[c] = r;
        nrm += fabsf(r);
    }
    float rinv = 1.0f / (nrm + 1e-7f);
    size_t base = ((size_t)b * Cdim) * 65536 + idx;
#pragma unroll
    for (int c = 0; c < Cdim; ++c) g_adj[base + (size_t)c * 65536] = sg[c] * rinv;
}

// ---------------------------------------------------------------------------
// K4: z[b*65+m][c*256+a] = sum_d adj[b,c,a,d]*src[m,d]; emit bf16 hi/lo split.
// ---------------------------------------------------------------------------
#define DT 32
__device__ __forceinline__ void store_split4(size_t off, const float* v) {
    __nv_bfloat16 h[4];
    __nv_bfloat162 hp0, hp1, lp0, lp1;
#pragma unroll
    for (int j = 0; j < 4; ++j) h[j] = __float2bfloat16(v[j]);
    hp0 = {h[0], h[1]}; hp1 = {h[2], h[3]};
    lp0 = {__float2bfloat16(v[0] - __bfloat162float(h[0])),
           __float2bfloat16(v[1] - __bfloat162float(h[1]))};
    lp1 = {__float2bfloat16(v[2] - __bfloat162float(h[2])),
           __float2bfloat16(v[3] - __bfloat162float(h[3]))};
    *(__nv_bfloat162*)&g_zh[off] = hp0; *(__nv_bfloat162*)&g_zh[off + 2] = hp1;
    *(__nv_bfloat162*)&g_zl[off] = lp0; *(__nv_bfloat162*)&g_zl[off + 2] = lp1;
}

__global__ void __launch_bounds__(256) k4_z(const float* __restrict__ x,
                                            const float* __restrict__ nb) {
    __shared__ float srcS[65 * DT];    // [row][dd]
    __shared__ float adjS[DT * 128];   // [dd][la]
    int atile = blockIdx.x;
    int c = blockIdx.y;
    int b = blockIdx.z;
    int t = threadIdx.x;
    int ag = t & 31;
    int mg = t >> 5;
    int a0 = atile * 128;
    int la = ag * 4;

    float acc[8][4] = {};
    float accx[4] = {};

    const float* xrow = x + ((size_t)b * Cdim + c) * Fdim;
    const float* nbase = nb + (((size_t)b * Ndim) * Cdim + c) * Fdim;
    const float* adjbase = g_adj + ((size_t)(b * Cdim + c)) * 65536 + a0;

    for (int d0 = 0; d0 < Fdim; d0 += DT) {
        for (int idx = t; idx < 65 * DT; idx += 256) {
            int row = idx >> 5, col = idx & (DT - 1);
            float v = (row == 0) ? xrow[d0 + col]
                                 : nbase[(size_t)(row - 1) * Kdim + d0 + col];
            srcS[idx] = v;
        }
        for (int idx = t; idx < DT * 128; idx += 256) {
            int dd = idx >> 7, l = idx & 127;
            adjS[idx] = adjbase[(size_t)(d0 + dd) * Fdim + l];
        }
        __syncthreads();
#pragma unroll 4
        for (int dd = 0; dd < DT; ++dd) {
            float4 av = *(const float4*)&adjS[dd * 128 + la];
#pragma unroll
            for (int j = 0; j < 8; ++j) {
                float s = srcS[(mg * 8 + j) * DT + dd];
                acc[j][0] += av.x * s; acc[j][1] += av.y * s;
                acc[j][2] += av.z * s; acc[j][3] += av.w * s;
            }
            if (mg == 7) {
                float s = srcS[64 * DT + dd];
                accx[0] += av.x * s; accx[1] += av.y * s;
                accx[2] += av.z * s; accx[3] += av.w * s;
            }
        }
        __syncthreads();
    }
#pragma unroll
    for (int j = 0; j < 8; ++j) {
        int m = mg * 8 + j;
        store_split4(((size_t)(b * 65 + m)) * Kdim + c * Fdim + a0 + la, acc[j]);
    }
    if (mg == 7)
        store_split4(((size_t)(b * 65 + 64)) * Kdim + c * Fdim + a0 + la, accx);
}

// ---------------------------------------------------------------------------
// K5: mma.sync bf16-split GEMM. out[row][o] = sum_k z[row][k]*Wc[o][k]
//     M=4224 (rows>=4160 zero), N=2048, K=2048. A=[m][k], B=[n][k] row-major
//     (B's [n][k] storage == mma col-major B; no .trans needed).
//     CTA 128x128, 8 warps (warp tile 64x32), BK=32 double-buffered SMEM.
//     Split: D += Ah*Bh + Ah*Bl + Al*Bh (fp32 accumulate).
// grid (16, 33) x 256, dynamic smem 81920
// ---------------------------------------------------------------------------
#define BK 32
#define SK 40                       // padded bf16 row stride (conflict-free ldmatrix)
#define ARRSZ (128 * SK)            // elements per array
#define STSZ  (4 * ARRSZ)           // elements per stage (Ah, Al, Bh, Bl)
__global__ void __launch_bounds__(256, 1) k5_mma(float* __restrict__ out) {
    extern __shared__ __nv_bfloat16 sm[];
    uint32_t sb = smem_u32(sm);
    int t = threadIdx.x;
    int w = t >> 5, lane = t & 31;
    int wm = w & 1, wn = w >> 1;            // warp tile: m = wm*64, n = wn*32
    int bn = blockIdx.x, bm = blockIdx.y;

    const __nv_bfloat16* bases[4];
    bases[0] = g_zh + (size_t)bm * 128 * Kdim;
    bases[1] = g_zl + (size_t)bm * 128 * Kdim;
    bases[2] = g_wh + (size_t)bn * 128 * Kdim;
    bases[3] = g_wl + (size_t)bn * 128 * Kdim;

    // per-thread gmem->smem chunks: per array, 2 chunks of 16B (8 bf16)
    int r0 = t >> 2, kc0 = t & 3;           // chunk 0: id = t
    int r1 = (t + 256) >> 2, kc1 = t & 3;   // chunk 1: id = t + 256

    float acc[4][4][4] = {};

    // ---- load stage 0 ----
    {
#pragma unroll
        for (int arr = 0; arr < 4; ++arr) {
            uint4 v0 = *(const uint4*)(bases[arr] + (size_t)r0 * Kdim + kc0 * 8);
            uint4 v1 = *(const uint4*)(bases[arr] + (size_t)r1 * Kdim + kc1 * 8);
            *(uint4*)&sm[arr * ARRSZ + r0 * SK + kc0 * 8] = v0;
            *(uint4*)&sm[arr * ARRSZ + r1 * SK + kc1 * 8] = v1;
        }
    }
    __syncthreads();

    const int NKT = Kdim / BK;   // 64
    for (int kt = 0; kt < NKT; ++kt) {
        int cur = kt & 1, nxt = cur ^ 1;
        // prefetch next chunk into registers
        uint4 pf[4][2];
        if (kt + 1 < NKT) {
            int k0 = (kt + 1) * BK;
#pragma unroll
            for (int arr = 0; arr < 4; ++arr) {
                pf[arr][0] = *(const uint4*)(bases[arr] + (size_t)r0 * Kdim + k0 + kc0 * 8);
                pf[arr][1] = *(const uint4*)(bases[arr] + (size_t)r1 * Kdim + k0 + kc1 * 8);
            }
        }
        // compute on cur
        uint32_t sA = sb + (uint32_t)(cur * STSZ) * 2;
        uint32_t sB = sA + (uint32_t)(2 * ARRSZ) * 2;
#pragma unroll
        for (int kk = 0; kk < 2; ++kk) {
            uint32_t afh[4][4], afl[4][4], bfh[4][2], bfl[4][2];
#pragma unroll
            for (int i = 0; i < 4; ++i) {
                int row = wm * 64 + i * 16 + (lane & 15);
                int col = kk * 16 + (lane >> 4) * 8;
                uint32_t off = (uint32_t)(row * SK + col) * 2;
                ldm_x4(sA + off, afh[i]);
                ldm_x4(sA + (uint32_t)ARRSZ * 2 + off, afl[i]);
            }
#pragma unroll
            for (int j = 0; j < 4; ++j) {
                int row = wn * 32 + j * 8 + (lane & 7);
                int col = kk * 16 + ((lane >> 3) & 1) * 8;
                uint32_t off = (uint32_t)(row * SK + col) * 2;
                ldm_x2(sB + off, bfh[j]);
                ldm_x2(sB + (uint32_t)ARRSZ * 2 + off, bfl[j]);
            }
#pragma unroll
            for (int i = 0; i < 4; ++i)
#pragma unroll
                for (int j = 0; j < 4; ++j) {
                    mma16816(acc[i][j], afh[i], bfh[j]);
                    mma16816(acc[i][j], afh[i], bfl[j]);
                    mma16816(acc[i][j], afl[i], bfh[j]);
                }
        }
        if (kt + 1 < NKT) {
            __syncthreads();   // all warps done reading stage nxt (their kt-1)
#pragma unroll
            for (int arr = 0; arr < 4; ++arr) {
                *(uint4*)&sm[nxt * STSZ + arr * ARRSZ + r0 * SK + kc0 * 8] = pf[arr][0];
                *(uint4*)&sm[nxt * STSZ + arr * ARRSZ + r1 * SK + kc1 * 8] = pf[arr][1];
            }
            __syncthreads();   // stores visible before next iteration reads
        }
    }

    // ---- epilogue: scatter rows to (x_out, n_out) layout ----
    int lq = lane >> 2, lr = lane & 3;
#pragma unroll
    for (int i = 0; i < 4; ++i) {
        int rowb = bm * 128 + wm * 64 + i * 16 + lq;
#pragma unroll
        for (int h = 0; h < 2; ++h) {
            int r = rowb + h * 8;
            if (r >= Mrows) continue;
            int b = r / 65, m = r % 65;
            size_t off = (m == 0) ? (size_t)b * 2048
                                  : (size_t)131072 + ((size_t)(b * 64 + m - 1)) * 2048;
            off += (size_t)bn * 128 + wn * 32 + lr * 2;
#pragma unroll
            for (int j = 0; j < 4; ++j) {
                float2 v = make_float2(acc[i][j][h * 2], acc[i][j][h * 2 + 1]);
                *(float2*)&out[off + j * 8] = v;
            }
        }
    }
}

// ---------------------------------------------------------------------------
extern "C" void kernel_launch(void* const* d_in, const int* in_sizes, int n_in,
                              void* d_out, int out_size) {
    const float* x  = (const float*)d_in[0];
    const float* nb = (const float*)d_in[1];
    const float* W1 = (const float*)d_in[2];
    const float* W2 = (const float*)d_in[3];
    const float* Wc = (const float*)d_in[4];
    float* out = (float*)d_out;

    cudaFuncSetAttribute(k5_mma, cudaFuncAttributeMaxDynamicSharedMemorySize,
                         2 * STSZ * (int)sizeof(__nv_bfloat16));

    k0_split<<<4096, 256>>>(Wc);
    k1_w    <<<dim3(64, 8),    256 >>>(x, nb, W1, W2);
    k2_t    <<<dim3(64, 2),   1024 >>>(nb);
    k3_adj  <<<dim3(64, 64),  1024 >>>(x);
    k4_z    <<<dim3(2, 8, 64), 256 >>>(x, nb);
    k5_mma  <<<dim3(16, 33),   256, 2 * STSZ * (int)sizeof(__nv_bfloat16)>>>(out);
}

// round 12
// speedup vs baseline: 2.4265x; 1.2508x over previous
#include <cuda_runtime.h>
#include <cuda_bf16.h>
#include <cstdint>
#include <cstddef>

// Problem dims
#define Bdim 64
#define Ndim 64
#define Cdim 8
#define Fdim 256
#define Kdim 2048           // C*F
#define Mrows 4160          // B*(N+1): row 0 of each b = x, rows 1..64 = neighbors
#define MrowsPad 4224       // 33*128 for GEMM tiling (padded rows stay zero)

// Scratch (static device globals; zero-initialized at module load).
__device__ float g_w[Bdim * Ndim];                                        // w[b,n]
__device__ float g_t[Bdim * Kdim];                                        // t[b,c,d]
__device__ __align__(256) __nv_bfloat16 g_ah[(size_t)Bdim * Cdim * 65536]; // adj hi [b][c][a][d]
__device__ __align__(256) __nv_bfloat16 g_al[(size_t)Bdim * Cdim * 65536]; // adj lo
__device__ __align__(256) __nv_bfloat16 g_zh[(size_t)MrowsPad * Kdim];    // z hi split
__device__ __align__(256) __nv_bfloat16 g_zl[(size_t)MrowsPad * Kdim];    // z lo split
__device__ __align__(256) __nv_bfloat16 g_wh[(size_t)Kdim * Kdim];        // Wc hi [o][k]
__device__ __align__(256) __nv_bfloat16 g_wl[(size_t)Kdim * Kdim];        // Wc lo [o][k]

// ---------------------------------------------------------------------------
// mma.sync helpers (arch-portable tensor core path; harness PTX target is
// plain sm_103 so tcgen05 is unavailable)
// ---------------------------------------------------------------------------
__device__ __forceinline__ uint32_t smem_u32(const void* p) {
    uint32_t a;
    asm("{ .reg .u64 t; cvta.to.shared.u64 t, %1; cvt.u32.u64 %0, t; }" : "=r"(a) : "l"(p));
    return a;
}
__device__ __forceinline__ void ldm_x4(uint32_t a, uint32_t f[4]) {
    asm volatile("ldmatrix.sync.aligned.m8n8.x4.shared.b16 {%0,%1,%2,%3}, [%4];"
                 : "=r"(f[0]), "=r"(f[1]), "=r"(f[2]), "=r"(f[3]) : "r"(a));
}
__device__ __forceinline__ void ldm_x2(uint32_t a, uint32_t f[2]) {
    asm volatile("ldmatrix.sync.aligned.m8n8.x2.shared.b16 {%0,%1}, [%2];"
                 : "=r"(f[0]), "=r"(f[1]) : "r"(a));
}
__device__ __forceinline__ void mma16816(float d[4], const uint32_t a[4],
                                         const uint32_t b[2]) {
    asm volatile(
        "mma.sync.aligned.m16n8k16.row.col.f32.bf16.bf16.f32 "
        "{%0,%1,%2,%3},{%4,%5,%6,%7},{%8,%9},{%0,%1,%2,%3};"
        : "+f"(d[0]), "+f"(d[1]), "+f"(d[2]), "+f"(d[3])
        : "r"(a[0]), "r"(a[1]), "r"(a[2]), "r"(a[3]), "r"(b[0]), "r"(b[1]));
}

// ---------------------------------------------------------------------------
// K0: split Wc (2048x2048 f32) into bf16 hi/lo. grid 4096 x 256 (float4/thread)
// ---------------------------------------------------------------------------
__global__ void k0_split(const float* __restrict__ Wc) {
    size_t i = (size_t)blockIdx.x * 256 + threadIdx.x;   // float4 index
    float4 v = ((const float4*)Wc)[i];
    __nv_bfloat16 h0 = __float2bfloat16(v.x), h1 = __float2bfloat16(v.y);
    __nv_bfloat16 h2 = __float2bfloat16(v.z), h3 = __float2bfloat16(v.w);
    __nv_bfloat162 hp0 = {h0, h1}, hp1 = {h2, h3};
    __nv_bfloat162 lp0 = {__float2bfloat16(v.x - __bfloat162float(h0)),
                          __float2bfloat16(v.y - __bfloat162float(h1))};
    __nv_bfloat162 lp1 = {__float2bfloat16(v.z - __bfloat162float(h2)),
                          __float2bfloat16(v.w - __bfloat162float(h3))};
    ((__nv_bfloat162*)g_wh)[i * 2] = hp0; ((__nv_bfloat162*)g_wh)[i * 2 + 1] = hp1;
    ((__nv_bfloat162*)g_wl)[i * 2] = lp0; ((__nv_bfloat162*)g_wl)[i * 2 + 1] = lp1;
}

// ---------------------------------------------------------------------------
// K1: w[b,n] = s1[b] * s2[b,n]
// ---------------------------------------------------------------------------
__global__ void k1_w(const float* __restrict__ x, const float* __restrict__ nb,
                     const float* __restrict__ W1, const float* __restrict__ W2) {
    __shared__ float w1s[Fdim], w2s[Fdim], red[256];
    int b = blockIdx.x, ng = blockIdx.y;
    int t = threadIdx.x;
    float a1 = 0.f, a2 = 0.f;
#pragma unroll
    for (int c = 0; c < Cdim; ++c) { a1 += W1[c * Fdim + t]; a2 += W2[c * Fdim + t]; }
    w1s[t] = a1; w2s[t] = a2;
    __syncthreads();
    float s = 0.f;
#pragma unroll
    for (int c = 0; c < Cdim; ++c) s += x[b * Kdim + c * Fdim + t] * w1s[t];
    red[t] = s; __syncthreads();
    for (int st = 128; st > 0; st >>= 1) {
        if (t < st) red[t] += red[t + st];
        __syncthreads();
    }
    float s1 = red[0];
    int warp = t >> 5, lane = t & 31;
    int n = ng * 8 + warp;
    const float* p = nb + ((size_t)(b * Ndim + n)) * Kdim;
    float acc = 0.f;
    for (int i = lane; i < Kdim; i += 32) acc += p[i] * w2s[i & (Fdim - 1)];
#pragma unroll
    for (int o = 16; o > 0; o >>= 1) acc += __shfl_xor_sync(0xffffffffu, acc, o);
    if (lane == 0) g_w[b * Ndim + n] = s1 * acc;
}

// ---------------------------------------------------------------------------
// K2: t[b,cd] = sum_n neighbor[b,n,cd] * w[b,n]     grid (64,2) x 1024
// ---------------------------------------------------------------------------
__global__ void k2_t(const float* __restrict__ nb) {
    __shared__ float ws[Ndim];
    int b = blockIdx.x;
    int cd = blockIdx.y * 1024 + threadIdx.x;
    if (threadIdx.x < Ndim) ws[threadIdx.x] = g_w[b * Ndim + threadIdx.x];
    __syncthreads();
    const float* p = nb + (size_t)b * Ndim * Kdim + cd;
    float acc = 0.f;
#pragma unroll 8
    for (int n = 0; n < Ndim; ++n) acc += p[(size_t)n * Kdim] * ws[n];
    g_t[b * Kdim + cd] = acc;
}

// ---------------------------------------------------------------------------
// K3: adj[b,c,a,d] = sgnroot(x_a t_d + x_d t_a) row-normalized over c.
//     Emits bf16 hi/lo planes directly (for the mma k4).
// ---------------------------------------------------------------------------
__global__ void k3_adj(const float* __restrict__ x) {
    __shared__ float xs[Kdim], ts[Kdim];
    int b = blockIdx.x, t = threadIdx.x;
    xs[t] = x[b * Kdim + t];               xs[t + 1024] = x[b * Kdim + t + 1024];
    ts[t] = g_t[b * Kdim + t];             ts[t + 1024] = g_t[b * Kdim + t + 1024];
    __syncthreads();
    int idx = blockIdx.y * 1024 + t;
    int a = idx >> 8, d = idx & 255;
    float sg[Cdim];
    float nrm = 0.f;
#pragma unroll
    for (int c = 0; c < Cdim; ++c) {
        float v = xs[c * Fdim + a] * ts[c * Fdim + d] + xs[c * Fdim + d] * ts[c * Fdim + a];
        float r;
        asm("sqrt.approx.f32 %0, %1;" : "=f"(r) : "f"(fmaxf(fabsf(v), 1e-8f)));
        r = copysignf(r, v);
        sg[c] = r;
        nrm += fabsf(r);
    }
    float rinv = 1.0f / (nrm + 1e-7f);
    size_t base = ((size_t)b * Cdim) * 65536 + idx;
#pragma unroll
    for (int c = 0; c < Cdim; ++c) {
        float val = sg[c] * rinv;
        __nv_bfloat16 h = __float2bfloat16(val);
        __nv_bfloat16 l = __float2bfloat16(val - __bfloat162float(h));
        g_ah[base + (size_t)c * 65536] = h;
        g_al[base + (size_t)c * 65536] = l;
    }
}

// ---------------------------------------------------------------------------
// K4: mma.sync bf16-split batched GEMM: per (b,c),
//     Z[m][a] = sum_d S[m][d] * adj[a][d]   (adj symmetric; [a][d] d-contig
//     is exactly mma col-major B). M=80 (row 0 = x, 1..64 = neighbor, 65..79
//     zero-pad), N=256, K=256, BK=32 double-buffered w/ register prefetch.
//     Emits z as bf16 hi/lo splits for K5.
// grid (8, 64) x 256, dynamic smem 107520
// ---------------------------------------------------------------------------
#define K4SK 40
#define K4_S_ARR (80 * K4SK)        // 3200 elems per S array
#define K4_B_ARR (256 * K4SK)       // 10240 elems per B array
#define K4_STG (2 * K4_S_ARR + 2 * K4_B_ARR)  // 26880 elems per stage
__global__ void __launch_bounds__(256, 1) k4_mma(const float* __restrict__ x,
                                                 const float* __restrict__ nb) {
    extern __shared__ __nv_bfloat16 sm4[];
    uint32_t sb = smem_u32(sm4);
    int t = threadIdx.x, w = t >> 5, lane = t & 31;
    int c = blockIdx.x, b = blockIdx.y;

    const float* xrow = x + ((size_t)b * Cdim + c) * Fdim;
    const float* nbase = nb + (((size_t)b * Ndim) * Cdim + c) * Fdim;
    const __nv_bfloat16* ah = g_ah + ((size_t)(b * Cdim + c)) * 65536;
    const __nv_bfloat16* al = g_al + ((size_t)(b * Cdim + c)) * 65536;

    float acc[5][4][4] = {};

    // S loader: 640 float4 chunks (80 rows x 8 chunks); thread handles
    // g = t, t+256, t+512(<640). B loader: 1024 16B chunks per array.
    auto load_S_direct = [&](int stg, int kt) {
#pragma unroll
        for (int j = 0; j < 3; ++j) {
            int g = t + j * 256;
            if (g >= 640) break;
            int row = g >> 3, col8 = (g & 7) * 4;
            float4 v = make_float4(0.f, 0.f, 0.f, 0.f);
            if (row == 0)       v = *(const float4*)(xrow + kt * 32 + col8);
            else if (row < 65)  v = *(const float4*)(nbase + (size_t)(row - 1) * Kdim + kt * 32 + col8);
            __nv_bfloat16 h0 = __float2bfloat16(v.x), h1 = __float2bfloat16(v.y);
            __nv_bfloat16 h2 = __float2bfloat16(v.z), h3 = __float2bfloat16(v.w);
            int o = stg * K4_STG + row * K4SK + col8;
            *(__nv_bfloat162*)&sm4[o]     = {h0, h1};
            *(__nv_bfloat162*)&sm4[o + 2] = {h2, h3};
            int ol = o + K4_S_ARR;
            *(__nv_bfloat162*)&sm4[ol]     = {__float2bfloat16(v.x - __bfloat162float(h0)),
                                              __float2bfloat16(v.y - __bfloat162float(h1))};
            *(__nv_bfloat162*)&sm4[ol + 2] = {__float2bfloat16(v.z - __bfloat162float(h2)),
                                              __float2bfloat16(v.w - __bfloat162float(h3))};
        }
    };
    auto load_B_direct = [&](int stg, int kt) {
#pragma unroll
        for (int j = 0; j < 4; ++j) {
            int id = t + j * 256;
            int row = id >> 2, kc = id & 3;
            uint4 vh = *(const uint4*)(ah + (size_t)row * 256 + kt * 32 + kc * 8);
            uint4 vl = *(const uint4*)(al + (size_t)row * 256 + kt * 32 + kc * 8);
            *(uint4*)&sm4[stg * K4_STG + 2 * K4_S_ARR + row * K4SK + kc * 8] = vh;
            *(uint4*)&sm4[stg * K4_STG + 2 * K4_S_ARR + K4_B_ARR + row * K4SK + kc * 8] = vl;
        }
    };

    load_S_direct(0, 0);
    load_B_direct(0, 0);
    __syncthreads();

    for (int kt = 0; kt < 8; ++kt) {
        int cur = kt & 1, nxt = cur ^ 1;
        // prefetch kt+1 into registers
        float4 psv[3];
        uint4 pbh[4], pbl[4];
        if (kt + 1 < 8) {
            int k0 = (kt + 1) * 32;
#pragma unroll
            for (int j = 0; j < 3; ++j) {
                int g = t + j * 256;
                psv[j] = make_float4(0.f, 0.f, 0.f, 0.f);
                if (g < 640) {
                    int row = g >> 3, col8 = (g & 7) * 4;
                    if (row == 0)      psv[j] = *(const float4*)(xrow + k0 + col8);
                    else if (row < 65) psv[j] = *(const float4*)(nbase + (size_t)(row - 1) * Kdim + k0 + col8);
                }
            }
#pragma unroll
            for (int j = 0; j < 4; ++j) {
                int id = t + j * 256;
                int row = id >> 2, kc = id & 3;
                pbh[j] = *(const uint4*)(ah + (size_t)row * 256 + k0 + kc * 8);
                pbl[j] = *(const uint4*)(al + (size_t)row * 256 + k0 + kc * 8);
            }
        }
        // compute on cur
        uint32_t aSh = sb + (uint32_t)(cur * K4_STG) * 2;
        uint32_t aSl = aSh + (uint32_t)K4_S_ARR * 2;
        uint32_t aBh = aSh + (uint32_t)(2 * K4_S_ARR) * 2;
        uint32_t aBl = aBh + (uint32_t)K4_B_ARR * 2;
#pragma unroll
        for (int kk = 0; kk < 2; ++kk) {
            uint32_t afh[5][4], afl[5][4], bfh[4][2], bfl[4][2];
#pragma unroll
            for (int i = 0; i < 5; ++i) {
                int row = i * 16 + (lane & 15);
                int col = kk * 16 + (lane >> 4) * 8;
                uint32_t off = (uint32_t)(row * K4SK + col) * 2;
                ldm_x4(aSh + off, afh[i]);
                ldm_x4(aSl + off, afl[i]);
            }
#pragma unroll
            for (int j = 0; j < 4; ++j) {
                int row = w * 32 + j * 8 + (lane & 7);
                int col = kk * 16 + ((lane >> 3) & 1) * 8;
                uint32_t off = (uint32_t)(row * K4SK + col) * 2;
                ldm_x2(aBh + off, bfh[j]);
                ldm_x2(aBl + off, bfl[j]);
            }
#pragma unroll
            for (int i = 0; i < 5; ++i)
#pragma unroll
                for (int j = 0; j < 4; ++j) {
                    mma16816(acc[i][j], afh[i], bfh[j]);
                    mma16816(acc[i][j], afh[i], bfl[j]);
                    mma16816(acc[i][j], afl[i], bfh[j]);
                }
        }
        if (kt + 1 < 8) {
            __syncthreads();
#pragma unroll
            for (int j = 0; j < 3; ++j) {
                int g = t + j * 256;
                if (g >= 640) break;
                int row = g >> 3, col8 = (g & 7) * 4;
                float4 v = psv[j];
                __nv_bfloat16 h0 = __float2bfloat16(v.x), h1 = __float2bfloat16(v.y);
                __nv_bfloat16 h2 = __float2bfloat16(v.z), h3 = __float2bfloat16(v.w);
                int o = nxt * K4_STG + row * K4SK + col8;
                *(__nv_bfloat162*)&sm4[o]     = {h0, h1};
                *(__nv_bfloat162*)&sm4[o + 2] = {h2, h3};
                int ol = o + K4_S_ARR;
                *(__nv_bfloat162*)&sm4[ol]     = {__float2bfloat16(v.x - __bfloat162float(h0)),
                                                  __float2bfloat16(v.y - __bfloat162float(h1))};
                *(__nv_bfloat162*)&sm4[ol + 2] = {__float2bfloat16(v.z - __bfloat162float(h2)),
                                                  __float2bfloat16(v.w - __bfloat162float(h3))};
            }
#pragma unroll
            for (int j = 0; j < 4; ++j) {
                int id = t + j * 256;
                int row = id >> 2, kc = id & 3;
                *(uint4*)&sm4[nxt * K4_STG + 2 * K4_S_ARR + row * K4SK + kc * 8] = pbh[j];
                *(uint4*)&sm4[nxt * K4_STG + 2 * K4_S_ARR + K4_B_ARR + row * K4SK + kc * 8] = pbl[j];
            }
            __syncthreads();
        }
    }

    // ---- epilogue: write z hi/lo splits ----
#pragma unroll
    for (int i = 0; i < 5; ++i) {
        int mb = i * 16 + (lane >> 2);
#pragma unroll
        for (int h = 0; h < 2; ++h) {
            int m = mb + h * 8;
            if (m >= 65) continue;
            size_t zoff = ((size_t)(b * 65 + m)) * Kdim + c * Fdim + w * 32 + (lane & 3) * 2;
#pragma unroll
            for (int j = 0; j < 4; ++j) {
                float v0 = acc[i][j][h * 2], v1 = acc[i][j][h * 2 + 1];
                __nv_bfloat16 h0 = __float2bfloat16(v0);
                __nv_bfloat16 h1 = __float2bfloat16(v1);
                *(__nv_bfloat162*)&g_zh[zoff + j * 8] = {h0, h1};
                *(__nv_bfloat162*)&g_zl[zoff + j * 8] =
                    {__float2bfloat16(v0 - __bfloat162float(h0)),
                     __float2bfloat16(v1 - __bfloat162float(h1))};
            }
        }
    }
}

// ---------------------------------------------------------------------------
// K5: mma.sync bf16-split GEMM. out[row][o] = sum_k z[row][k]*Wc[o][k]
//     (unchanged from R10 — validated at 625 µs total, rel_err 8e-6)
// ---------------------------------------------------------------------------
#define BK 32
#define SK 40
#define ARRSZ (128 * SK)
#define STSZ  (4 * ARRSZ)
__global__ void __launch_bounds__(256, 1) k5_mma(float* __restrict__ out) {
    extern __shared__ __nv_bfloat16 sm[];
    uint32_t sb = smem_u32(sm);
    int t = threadIdx.x;
    int w = t >> 5, lane = t & 31;
    int wm = w & 1, wn = w >> 1;
    int bn = blockIdx.x, bm = blockIdx.y;

    const __nv_bfloat16* bases[4];
    bases[0] = g_zh + (size_t)bm * 128 * Kdim;
    bases[1] = g_zl + (size_t)bm * 128 * Kdim;
    bases[2] = g_wh + (size_t)bn * 128 * Kdim;
    bases[3] = g_wl + (size_t)bn * 128 * Kdim;

    int r0 = t >> 2, kc0 = t & 3;
    int r1 = (t + 256) >> 2, kc1 = t & 3;

    float acc[4][4][4] = {};

    {
#pragma unroll
        for (int arr = 0; arr < 4; ++arr) {
            uint4 v0 = *(const uint4*)(bases[arr] + (size_t)r0 * Kdim + kc0 * 8);
            uint4 v1 = *(const uint4*)(bases[arr] + (size_t)r1 * Kdim + kc1 * 8);
            *(uint4*)&sm[arr * ARRSZ + r0 * SK + kc0 * 8] = v0;
            *(uint4*)&sm[arr * ARRSZ + r1 * SK + kc1 * 8] = v1;
        }
    }
    __syncthreads();

    const int NKT = Kdim / BK;
    for (int kt = 0; kt < NKT; ++kt) {
        int cur = kt & 1, nxt = cur ^ 1;
        uint4 pf[4][2];
        if (kt + 1 < NKT) {
            int k0 = (kt + 1) * BK;
#pragma unroll
            for (int arr = 0; arr < 4; ++arr) {
                pf[arr][0] = *(const uint4*)(bases[arr] + (size_t)r0 * Kdim + k0 + kc0 * 8);
                pf[arr][1] = *(const uint4*)(bases[arr] + (size_t)r1 * Kdim + k0 + kc1 * 8);
            }
        }
        uint32_t sA = sb + (uint32_t)(cur * STSZ) * 2;
        uint32_t sB = sA + (uint32_t)(2 * ARRSZ) * 2;
#pragma unroll
        for (int kk = 0; kk < 2; ++kk) {
            uint32_t afh[4][4], afl[4][4], bfh[4][2], bfl[4][2];
#pragma unroll
            for (int i = 0; i < 4; ++i) {
                int row = wm * 64 + i * 16 + (lane & 15);
                int col = kk * 16 + (lane >> 4) * 8;
                uint32_t off = (uint32_t)(row * SK + col) * 2;
                ldm_x4(sA + off, afh[i]);
                ldm_x4(sA + (uint32_t)ARRSZ * 2 + off, afl[i]);
            }
#pragma unroll
            for (int j = 0; j < 4; ++j) {
                int row = wn * 32 + j * 8 + (lane & 7);
                int col = kk * 16 + ((lane >> 3) & 1) * 8;
                uint32_t off = (uint32_t)(row * SK + col) * 2;
                ldm_x2(sB + off, bfh[j]);
                ldm_x2(sB + (uint32_t)ARRSZ * 2 + off, bfl[j]);
            }
#pragma unroll
            for (int i = 0; i < 4; ++i)
#pragma unroll
                for (int j = 0; j < 4; ++j) {
                    mma16816(acc[i][j], afh[i], bfh[j]);
                    mma16816(acc[i][j], afh[i], bfl[j]);
                    mma16816(acc[i][j], afl[i], bfh[j]);
                }
        }
        if (kt + 1 < NKT) {
            __syncthreads();
#pragma unroll
            for (int arr = 0; arr < 4; ++arr) {
                *(uint4*)&sm[nxt * STSZ + arr * ARRSZ + r0 * SK + kc0 * 8] = pf[arr][0];
                *(uint4*)&sm[nxt * STSZ + arr * ARRSZ + r1 * SK + kc1 * 8] = pf[arr][1];
            }
            __syncthreads();
        }
    }

    int lq = lane >> 2, lr = lane & 3;
#pragma unroll
    for (int i = 0; i < 4; ++i) {
        int rowb = bm * 128 + wm * 64 + i * 16 + lq;
#pragma unroll
        for (int h = 0; h < 2; ++h) {
            int r = rowb + h * 8;
            if (r >= Mrows) continue;
            int b = r / 65, m = r % 65;
            size_t off = (m == 0) ? (size_t)b * 2048
                                  : (size_t)131072 + ((size_t)(b * 64 + m - 1)) * 2048;
            off += (size_t)bn * 128 + wn * 32 + lr * 2;
#pragma unroll
            for (int j = 0; j < 4; ++j) {
                float2 v = make_float2(acc[i][j][h * 2], acc[i][j][h * 2 + 1]);
                *(float2*)&out[off + j * 8] = v;
            }
        }
    }
}

// ---------------------------------------------------------------------------
extern "C" void kernel_launch(void* const* d_in, const int* in_sizes, int n_in,
                              void* d_out, int out_size) {
    const float* x  = (const float*)d_in[0];
    const float* nb = (const float*)d_in[1];
    const float* W1 = (const float*)d_in[2];
    const float* W2 = (const float*)d_in[3];
    const float* Wc = (const float*)d_in[4];
    float* out = (float*)d_out;

    cudaFuncSetAttribute(k5_mma, cudaFuncAttributeMaxDynamicSharedMemorySize,
                         2 * STSZ * (int)sizeof(__nv_bfloat16));
    cudaFuncSetAttribute(k4_mma, cudaFuncAttributeMaxDynamicSharedMemorySize,
                         2 * K4_STG * (int)sizeof(__nv_bfloat16));

    k0_split<<<4096, 256>>>(Wc);
    k1_w    <<<dim3(64, 8),   256 >>>(x, nb, W1, W2);
    k2_t    <<<dim3(64, 2),  1024 >>>(nb);
    k3_adj  <<<dim3(64, 64), 1024 >>>(x);
    k4_mma  <<<dim3(8, 64),   256, 2 * K4_STG * (int)sizeof(__nv_bfloat16)>>>(x, nb);
    k5_mma  <<<dim3(16, 33),  256, 2 * STSZ * (int)sizeof(__nv_bfloat16)>>>(out);
}

// round 14
// speedup vs baseline: 2.7013x; 1.1132x over previous
#include <cuda_runtime.h>
#include <cuda_bf16.h>
#include <cstdint>
#include <cstddef>

// Problem dims
#define Bdim 64
#define Ndim 64
#define Cdim 8
#define Fdim 256
#define Kdim 2048           // C*F
#define Mrows 4160          // B*(N+1): row 0 of each b = x, rows 1..64 = neighbors
#define MrowsPad 4224       // 33*128 for GEMM tiling (padded rows stay zero)

// Scratch (static device globals; zero-initialized at module load).
__device__ float g_w[Bdim * Ndim];                                        // w[b,n]
__device__ float g_t[Bdim * Kdim];                                        // t[b,c,d]
__device__ __align__(256) __nv_bfloat16 g_ah[(size_t)Bdim * Cdim * 65536]; // adj hi [b][c][a][d]
__device__ __align__(256) __nv_bfloat16 g_al[(size_t)Bdim * Cdim * 65536]; // adj lo
__device__ __align__(256) __nv_bfloat16 g_zh[(size_t)MrowsPad * Kdim];    // z hi split
__device__ __align__(256) __nv_bfloat16 g_zl[(size_t)MrowsPad * Kdim];    // z lo split
__device__ __align__(256) __nv_bfloat16 g_wh[(size_t)Kdim * Kdim];        // Wc hi [o][k]
__device__ __align__(256) __nv_bfloat16 g_wl[(size_t)Kdim * Kdim];        // Wc lo [o][k]

// ---------------------------------------------------------------------------
// mma.sync / cp.async helpers (arch-portable tensor core path; harness PTX
// target is plain sm_103 so tcgen05 is unavailable)
// ---------------------------------------------------------------------------
__device__ __forceinline__ uint32_t smem_u32(const void* p) {
    uint32_t a;
    asm("{ .reg .u64 t; cvta.to.shared.u64 t, %1; cvt.u32.u64 %0, t; }" : "=r"(a) : "l"(p));
    return a;
}
__device__ __forceinline__ void ldm_x4(uint32_t a, uint32_t f[4]) {
    asm volatile("ldmatrix.sync.aligned.m8n8.x4.shared.b16 {%0,%1,%2,%3}, [%4];"
                 : "=r"(f[0]), "=r"(f[1]), "=r"(f[2]), "=r"(f[3]) : "r"(a));
}
__device__ __forceinline__ void ldm_x2(uint32_t a, uint32_t f[2]) {
    asm volatile("ldmatrix.sync.aligned.m8n8.x2.shared.b16 {%0,%1}, [%2];"
                 : "=r"(f[0]), "=r"(f[1]) : "r"(a));
}
__device__ __forceinline__ void mma16816(float d[4], const uint32_t a[4],
                                         const uint32_t b[2]) {
    asm volatile(
        "mma.sync.aligned.m16n8k16.row.col.f32.bf16.bf16.f32 "
        "{%0,%1,%2,%3},{%4,%5,%6,%7},{%8,%9},{%0,%1,%2,%3};"
        : "+f"(d[0]), "+f"(d[1]), "+f"(d[2]), "+f"(d[3])
        : "r"(a[0]), "r"(a[1]), "r"(a[2]), "r"(a[3]), "r"(b[0]), "r"(b[1]));
}
__device__ __forceinline__ void cp16(uint32_t smem_dst, const void* gsrc) {
    asm volatile("cp.async.cg.shared.global [%0], [%1], 16;"
                 :: "r"(smem_dst), "l"(gsrc) : "memory");
}
#define CP_COMMIT() asm volatile("cp.async.commit_group;" ::: "memory")
#define CP_WAIT0()  asm volatile("cp.async.wait_group 0;" ::: "memory")

// ---------------------------------------------------------------------------
// K0: split Wc (2048x2048 f32) into bf16 hi/lo. grid 4096 x 256 (float4/thread)
// ---------------------------------------------------------------------------
__global__ void k0_split(const float* __restrict__ Wc) {
    size_t i = (size_t)blockIdx.x * 256 + threadIdx.x;   // float4 index
    float4 v = ((const float4*)Wc)[i];
    __nv_bfloat16 h0 = __float2bfloat16(v.x), h1 = __float2bfloat16(v.y);
    __nv_bfloat16 h2 = __float2bfloat16(v.z), h3 = __float2bfloat16(v.w);
    __nv_bfloat162 hp0 = {h0, h1}, hp1 = {h2, h3};
    __nv_bfloat162 lp0 = {__float2bfloat16(v.x - __bfloat162float(h0)),
                          __float2bfloat16(v.y - __bfloat162float(h1))};
    __nv_bfloat162 lp1 = {__float2bfloat16(v.z - __bfloat162float(h2)),
                          __float2bfloat16(v.w - __bfloat162float(h3))};
    ((__nv_bfloat162*)g_wh)[i * 2] = hp0; ((__nv_bfloat162*)g_wh)[i * 2 + 1] = hp1;
    ((__nv_bfloat162*)g_wl)[i * 2] = lp0; ((__nv_bfloat162*)g_wl)[i * 2 + 1] = lp1;
}

// ---------------------------------------------------------------------------
// K1: w[b,n] = s1[b] * s2[b,n]
// ---------------------------------------------------------------------------
__global__ void k1_w(const float* __restrict__ x, const float* __restrict__ nb,
                     const float* __restrict__ W1, const float* __restrict__ W2) {
    __shared__ float w1s[Fdim], w2s[Fdim], red[256];
    int b = blockIdx.x, ng = blockIdx.y;
    int t = threadIdx.x;
    float a1 = 0.f, a2 = 0.f;
#pragma unroll
    for (int c = 0; c < Cdim; ++c) { a1 += W1[c * Fdim + t]; a2 += W2[c * Fdim + t]; }
    w1s[t] = a1; w2s[t] = a2;
    __syncthreads();
    float s = 0.f;
#pragma unroll
    for (int c = 0; c < Cdim; ++c) s += x[b * Kdim + c * Fdim + t] * w1s[t];
    red[t] = s; __syncthreads();
    for (int st = 128; st > 0; st >>= 1) {
        if (t < st) red[t] += red[t + st];
        __syncthreads();
    }
    float s1 = red[0];
    int warp = t >> 5, lane = t & 31;
    int n = ng * 8 + warp;
    const float* p = nb + ((size_t)(b * Ndim + n)) * Kdim;
    float acc = 0.f;
    for (int i = lane; i < Kdim; i += 32) acc += p[i] * w2s[i & (Fdim - 1)];
#pragma unroll
    for (int o = 16; o > 0; o >>= 1) acc += __shfl_xor_sync(0xffffffffu, acc, o);
    if (lane == 0) g_w[b * Ndim + n] = s1 * acc;
}

// ---------------------------------------------------------------------------
// K2: t[b,cd] = sum_n neighbor[b,n,cd] * w[b,n]     grid (64,2) x 1024
// ---------------------------------------------------------------------------
__global__ void k2_t(const float* __restrict__ nb) {
    __shared__ float ws[Ndim];
    int b = blockIdx.x;
    int cd = blockIdx.y * 1024 + threadIdx.x;
    if (threadIdx.x < Ndim) ws[threadIdx.x] = g_w[b * Ndim + threadIdx.x];
    __syncthreads();
    const float* p = nb + (size_t)b * Ndim * Kdim + cd;
    float acc = 0.f;
#pragma unroll 8
    for (int n = 0; n < Ndim; ++n) acc += p[(size_t)n * Kdim] * ws[n];
    g_t[b * Kdim + cd] = acc;
}

// ---------------------------------------------------------------------------
// K3: adj = sgnroot(x_a t_d + x_d t_a) row-normalized over c; bf16 hi/lo out.
//     Each thread handles 2 consecutive d's -> bf16x2 (4B) coalesced stores.
// grid (64, 32) x 1024
// ---------------------------------------------------------------------------
__global__ void k3_adj(const float* __restrict__ x) {
    __shared__ float xs[Kdim], ts[Kdim];
    int b = blockIdx.x, t = threadIdx.x;
    xs[t] = x[b * Kdim + t];               xs[t + 1024] = x[b * Kdim + t + 1024];
    ts[t] = g_t[b * Kdim + t];             ts[t + 1024] = g_t[b * Kdim + t + 1024];
    __syncthreads();
    int idx2 = blockIdx.y * 2048 + t * 2;
    int a = idx2 >> 8, d0 = idx2 & 255;    // d1 = d0 + 1
    float sg0[Cdim], sg1[Cdim];
    float nrm0 = 0.f, nrm1 = 0.f;
#pragma unroll
    for (int c = 0; c < Cdim; ++c) {
        float xa = xs[c * Fdim + a], ta = ts[c * Fdim + a];
        float v0 = xa * ts[c * Fdim + d0]     + xs[c * Fdim + d0]     * ta;
        float v1 = xa * ts[c * Fdim + d0 + 1] + xs[c * Fdim + d0 + 1] * ta;
        float r0, r1;
        asm("sqrt.approx.f32 %0, %1;" : "=f"(r0) : "f"(fmaxf(fabsf(v0), 1e-8f)));
        asm("sqrt.approx.f32 %0, %1;" : "=f"(r1) : "f"(fmaxf(fabsf(v1), 1e-8f)));
        r0 = copysignf(r0, v0); r1 = copysignf(r1, v1);
        sg0[c] = r0; sg1[c] = r1;
        nrm0 += fabsf(r0); nrm1 += fabsf(r1);
    }
    float ri0 = 1.0f / (nrm0 + 1e-7f), ri1 = 1.0f / (nrm1 + 1e-7f);
    size_t base = ((size_t)b * Cdim) * 65536 + idx2;
#pragma unroll
    for (int c = 0; c < Cdim; ++c) {
        float v0 = sg0[c] * ri0, v1 = sg1[c] * ri1;
        __nv_bfloat16 h0 = __float2bfloat16(v0);
        __nv_bfloat16 h1 = __float2bfloat16(v1);
        *(__nv_bfloat162*)&g_ah[base + (size_t)c * 65536] = {h0, h1};
        *(__nv_bfloat162*)&g_al[base + (size_t)c * 65536] =
            {__float2bfloat16(v0 - __bfloat162float(h0)),
             __float2bfloat16(v1 - __bfloat162float(h1))};
    }
}

// ---------------------------------------------------------------------------
// K4: mma.sync bf16-split batched GEMM: per (b,c),
//     Z[m][a] = sum_d S[m][d] * adj[a][d]. M=80 (pad), N=256, K=256, BK=32
//     double-buffered w/ register prefetch. (Unchanged — validated R12.)
// grid (8, 64) x 256, dynamic smem 107520
// ---------------------------------------------------------------------------
#define K4SK 40
#define K4_S_ARR (80 * K4SK)
#define K4_B_ARR (256 * K4SK)
#define K4_STG (2 * K4_S_ARR + 2 * K4_B_ARR)
__global__ void __launch_bounds__(256, 1) k4_mma(const float* __restrict__ x,
                                                 const float* __restrict__ nb) {
    extern __shared__ __nv_bfloat16 sm4[];
    uint32_t sb = smem_u32(sm4);
    int t = threadIdx.x, w = t >> 5, lane = t & 31;
    int c = blockIdx.x, b = blockIdx.y;

    const float* xrow = x + ((size_t)b * Cdim + c) * Fdim;
    const float* nbase = nb + (((size_t)b * Ndim) * Cdim + c) * Fdim;
    const __nv_bfloat16* ah = g_ah + ((size_t)(b * Cdim + c)) * 65536;
    const __nv_bfloat16* al = g_al + ((size_t)(b * Cdim + c)) * 65536;

    float acc[5][4][4] = {};

    auto load_S_direct = [&](int stg, int kt) {
#pragma unroll
        for (int j = 0; j < 3; ++j) {
            int g = t + j * 256;
            if (g >= 640) break;
            int row = g >> 3, col8 = (g & 7) * 4;
            float4 v = make_float4(0.f, 0.f, 0.f, 0.f);
            if (row == 0)       v = *(const float4*)(xrow + kt * 32 + col8);
            else if (row < 65)  v = *(const float4*)(nbase + (size_t)(row - 1) * Kdim + kt * 32 + col8);
            __nv_bfloat16 h0 = __float2bfloat16(v.x), h1 = __float2bfloat16(v.y);
            __nv_bfloat16 h2 = __float2bfloat16(v.z), h3 = __float2bfloat16(v.w);
            int o = stg * K4_STG + row * K4SK + col8;
            *(__nv_bfloat162*)&sm4[o]     = {h0, h1};
            *(__nv_bfloat162*)&sm4[o + 2] = {h2, h3};
            int ol = o + K4_S_ARR;
            *(__nv_bfloat162*)&sm4[ol]     = {__float2bfloat16(v.x - __bfloat162float(h0)),
                                              __float2bfloat16(v.y - __bfloat162float(h1))};
            *(__nv_bfloat162*)&sm4[ol + 2] = {__float2bfloat16(v.z - __bfloat162float(h2)),
                                              __float2bfloat16(v.w - __bfloat162float(h3))};
        }
    };
    auto load_B_direct = [&](int stg, int kt) {
#pragma unroll
        for (int j = 0; j < 4; ++j) {
            int id = t + j * 256;
            int row = id >> 2, kc = id & 3;
            uint4 vh = *(const uint4*)(ah + (size_t)row * 256 + kt * 32 + kc * 8);
            uint4 vl = *(const uint4*)(al + (size_t)row * 256 + kt * 32 + kc * 8);
            *(uint4*)&sm4[stg * K4_STG + 2 * K4_S_ARR + row * K4SK + kc * 8] = vh;
            *(uint4*)&sm4[stg * K4_STG + 2 * K4_S_ARR + K4_B_ARR + row * K4SK + kc * 8] = vl;
        }
    };

    load_S_direct(0, 0);
    load_B_direct(0, 0);
    __syncthreads();

    for (int kt = 0; kt < 8; ++kt) {
        int cur = kt & 1, nxt = cur ^ 1;
        float4 psv[3];
        uint4 pbh[4], pbl[4];
        if (kt + 1 < 8) {
            int k0 = (kt + 1) * 32;
#pragma unroll
            for (int j = 0; j < 3; ++j) {
                int g = t + j * 256;
                psv[j] = make_float4(0.f, 0.f, 0.f, 0.f);
                if (g < 640) {
                    int row = g >> 3, col8 = (g & 7) * 4;
                    if (row == 0)      psv[j] = *(const float4*)(xrow + k0 + col8);
                    else if (row < 65) psv[j] = *(const float4*)(nbase + (size_t)(row - 1) * Kdim + k0 + col8);
                }
            }
#pragma unroll
            for (int j = 0; j < 4; ++j) {
                int id = t + j * 256;
                int row = id >> 2, kc = id & 3;
                pbh[j] = *(const uint4*)(ah + (size_t)row * 256 + k0 + kc * 8);
                pbl[j] = *(const uint4*)(al + (size_t)row * 256 + k0 + kc * 8);
            }
        }
        uint32_t aSh = sb + (uint32_t)(cur * K4_STG) * 2;
        uint32_t aSl = aSh + (uint32_t)K4_S_ARR * 2;
        uint32_t aBh = aSh + (uint32_t)(2 * K4_S_ARR) * 2;
        uint32_t aBl = aBh + (uint32_t)K4_B_ARR * 2;
#pragma unroll
        for (int kk = 0; kk < 2; ++kk) {
            uint32_t afh[5][4], afl[5][4], bfh[4][2], bfl[4][2];
#pragma unroll
            for (int i = 0; i < 5; ++i) {
                int row = i * 16 + (lane & 15);
                int col = kk * 16 + (lane >> 4) * 8;
                uint32_t off = (uint32_t)(row * K4SK + col) * 2;
                ldm_x4(aSh + off, afh[i]);
                ldm_x4(aSl + off, afl[i]);
            }
#pragma unroll
            for (int j = 0; j < 4; ++j) {
                int row = w * 32 + j * 8 + (lane & 7);
                int col = kk * 16 + ((lane >> 3) & 1) * 8;
                uint32_t off = (uint32_t)(row * K4SK + col) * 2;
                ldm_x2(aBh + off, bfh[j]);
                ldm_x2(aBl + off, bfl[j]);
            }
#pragma unroll
            for (int i = 0; i < 5; ++i)
#pragma unroll
                for (int j = 0; j < 4; ++j) {
                    mma16816(acc[i][j], afh[i], bfh[j]);
                    mma16816(acc[i][j], afh[i], bfl[j]);
                    mma16816(acc[i][j], afl[i], bfh[j]);
                }
        }
        if (kt + 1 < 8) {
            __syncthreads();
#pragma unroll
            for (int j = 0; j < 3; ++j) {
                int g = t + j * 256;
                if (g >= 640) break;
                int row = g >> 3, col8 = (g & 7) * 4;
                float4 v = psv[j];
                __nv_bfloat16 h0 = __float2bfloat16(v.x), h1 = __float2bfloat16(v.y);
                __nv_bfloat16 h2 = __float2bfloat16(v.z), h3 = __float2bfloat16(v.w);
                int o = nxt * K4_STG + row * K4SK + col8;
                *(__nv_bfloat162*)&sm4[o]     = {h0, h1};
                *(__nv_bfloat162*)&sm4[o + 2] = {h2, h3};
                int ol = o + K4_S_ARR;
                *(__nv_bfloat162*)&sm4[ol]     = {__float2bfloat16(v.x - __bfloat162float(h0)),
                                                  __float2bfloat16(v.y - __bfloat162float(h1))};
                *(__nv_bfloat162*)&sm4[ol + 2] = {__float2bfloat16(v.z - __bfloat162float(h2)),
                                                  __float2bfloat16(v.w - __bfloat162float(h3))};
            }
#pragma unroll
            for (int j = 0; j < 4; ++j) {
                int id = t + j * 256;
                int row = id >> 2, kc = id & 3;
                *(uint4*)&sm4[nxt * K4_STG + 2 * K4_S_ARR + row * K4SK + kc * 8] = pbh[j];
                *(uint4*)&sm4[nxt * K4_STG + 2 * K4_S_ARR + K4_B_ARR + row * K4SK + kc * 8] = pbl[j];
            }
            __syncthreads();
        }
    }

#pragma unroll
    for (int i = 0; i < 5; ++i) {
        int mb = i * 16 + (lane >> 2);
#pragma unroll
        for (int h = 0; h < 2; ++h) {
            int m = mb + h * 8;
            if (m >= 65) continue;
            size_t zoff = ((size_t)(b * 65 + m)) * Kdim + c * Fdim + w * 32 + (lane & 3) * 2;
#pragma unroll
            for (int j = 0; j < 4; ++j) {
                float v0 = acc[i][j][h * 2], v1 = acc[i][j][h * 2 + 1];
                __nv_bfloat16 h0 = __float2bfloat16(v0);
                __nv_bfloat16 h1 = __float2bfloat16(v1);
                *(__nv_bfloat162*)&g_zh[zoff + j * 8] = {h0, h1};
                *(__nv_bfloat162*)&g_zl[zoff + j * 8] =
                    {__float2bfloat16(v0 - __bfloat162float(h0)),
                     __float2bfloat16(v1 - __bfloat162float(h1))};
            }
        }
    }
}

// ---------------------------------------------------------------------------
// K5: mma.sync bf16-split GEMM, BK=64, cp.async 2-stage pipeline.
//     out[row][o] = sum_k z[row][k]*Wc[o][k]. M=4224, N=2048, K=2048.
//     CTA 128x128, 8 warps (64x32 each). Split: D += Ah*Bh + Ah*Bl + Al*Bh.
// grid (16, 33) x 256, dynamic smem 147456
// ---------------------------------------------------------------------------
#define BK 64
#define SK 72                       // padded row stride (144B: 8 rows cover all banks)
#define ARRSZ (128 * SK)            // 9216 elems per array
#define STSZ  (4 * ARRSZ)           // 36864 elems per stage
__global__ void __launch_bounds__(256, 1) k5_mma(float* __restrict__ out) {
    extern __shared__ __nv_bfloat16 sm[];
    uint32_t sb = smem_u32(sm);
    int t = threadIdx.x;
    int w = t >> 5, lane = t & 31;
    int wm = w & 1, wn = w >> 1;            // warp tile: m = wm*64, n = wn*32
    int bn = blockIdx.x, bm = blockIdx.y;

    const __nv_bfloat16* bases[4];
    bases[0] = g_zh + (size_t)bm * 128 * Kdim;
    bases[1] = g_zl + (size_t)bm * 128 * Kdim;
    bases[2] = g_wh + (size_t)bn * 128 * Kdim;
    bases[3] = g_wl + (size_t)bn * 128 * Kdim;

    float acc[4][4][4] = {};

    // stage issue: 4096 16B chunks (4 arrays x 128 rows x 8 kc); 16/thread.
    auto issue_stage = [&](int stg, int kt) {
#pragma unroll
        for (int j = 0; j < 16; ++j) {
            int arr = j >> 2;
            int rem = (j & 3) * 256 + t;        // 0..1023
            int row = rem >> 3, kc = rem & 7;
            const void* src = bases[arr] + (size_t)row * Kdim + kt * BK + kc * 8;
            uint32_t dst = sb + (uint32_t)(stg * STSZ + arr * ARRSZ + row * SK + kc * 8) * 2;
            cp16(dst, src);
        }
        CP_COMMIT();
    };

    issue_stage(0, 0);
    CP_WAIT0();
    __syncthreads();

    const int NKT = Kdim / BK;   // 32
    for (int kt = 0; kt < NKT; ++kt) {
        int cur = kt & 1, nxt = cur ^ 1;
        if (kt + 1 < NKT) issue_stage(nxt, kt + 1);
        uint32_t sA = sb + (uint32_t)(cur * STSZ) * 2;
        uint32_t sB = sA + (uint32_t)(2 * ARRSZ) * 2;
#pragma unroll
        for (int kk = 0; kk < 4; ++kk) {
            uint32_t afh[4][4], afl[4][4], bfh[4][2], bfl[4][2];
#pragma unroll
            for (int i = 0; i < 4; ++i) {
                int row = wm * 64 + i * 16 + (lane & 15);
                int col = kk * 16 + (lane >> 4) * 8;
                uint32_t off = (uint32_t)(row * SK + col) * 2;
                ldm_x4(sA + off, afh[i]);
                ldm_x4(sA + (uint32_t)ARRSZ * 2 + off, afl[i]);
            }
#pragma unroll
            for (int j = 0; j < 4; ++j) {
                int row = wn * 32 + j * 8 + (lane & 7);
                int col = kk * 16 + ((lane >> 3) & 1) * 8;
                uint32_t off = (uint32_t)(row * SK + col) * 2;
                ldm_x2(sB + off, bfh[j]);
                ldm_x2(sB + (uint32_t)ARRSZ * 2 + off, bfl[j]);
            }
#pragma unroll
            for (int i = 0; i < 4; ++i)
#pragma unroll
                for (int j = 0; j < 4; ++j) {
                    mma16816(acc[i][j], afh[i], bfh[j]);
                    mma16816(acc[i][j], afh[i], bfl[j]);
                    mma16816(acc[i][j], afl[i], bfh[j]);
                }
        }
        if (kt + 1 < NKT) {
            CP_WAIT0();
            __syncthreads();
        }
    }

    // ---- epilogue: scatter rows to (x_out, n_out) layout ----
    int lq = lane >> 2, lr = lane & 3;
#pragma unroll
    for (int i = 0; i < 4; ++i) {
        int rowb = bm * 128 + wm * 64 + i * 16 + lq;
#pragma unroll
        for (int h = 0; h < 2; ++h) {
            int r = rowb + h * 8;
            if (r >= Mrows) continue;
            int b = r / 65, m = r % 65;
            size_t off = (m == 0) ? (size_t)b * 2048
                                  : (size_t)131072 + ((size_t)(b * 64 + m - 1)) * 2048;
            off += (size_t)bn * 128 + wn * 32 + lr * 2;
#pragma unroll
            for (int j = 0; j < 4; ++j) {
                float2 v = make_float2(acc[i][j][h * 2], acc[i][j][h * 2 + 1]);
                *(float2*)&out[off + j * 8] = v;
            }
        }
    }
}

// ---------------------------------------------------------------------------
extern "C" void kernel_launch(void* const* d_in, const int* in_sizes, int n_in,
                              void* d_out, int out_size) {
    const float* x  = (const float*)d_in[0];
    const float* nb = (const float*)d_in[1];
    const float* W1 = (const float*)d_in[2];
    const float* W2 = (const float*)d_in[3];
    const float* Wc = (const float*)d_in[4];
    float* out = (float*)d_out;

    cudaFuncSetAttribute(k5_mma, cudaFuncAttributeMaxDynamicSharedMemorySize,
                         2 * STSZ * (int)sizeof(__nv_bfloat16));
    cudaFuncSetAttribute(k4_mma, cudaFuncAttributeMaxDynamicSharedMemorySize,
                         2 * K4_STG * (int)sizeof(__nv_bfloat16));

    k0_split<<<4096, 256>>>(Wc);
    k1_w    <<<dim3(64, 8),   256 >>>(x, nb, W1, W2);
    k2_t    <<<dim3(64, 2),  1024 >>>(nb);
    k3_adj  <<<dim3(64, 32), 1024 >>>(x);
    k4_mma  <<<dim3(8, 64),   256, 2 * K4_STG * (int)sizeof(__nv_bfloat16)>>>(x, nb);
    k5_mma  <<<dim3(16, 33),  256, 2 * STSZ * (int)sizeof(__nv_bfloat16)>>>(out);
}